// round 1
// baseline (speedup 1.0000x reference)
#include <cuda_runtime.h>
#include <math.h>

// Problem constants
#define N_TOK 4096
#define HDIM  768
#define FDIM  3072
#define EC    4
#define EU    4
#define CAP   1024

// GEMM tiling
#define BM 128
#define BN 128
#define BK 8
#define MAXT 36                 // max m-tiles: 4096/128 + 4 (segment padding)
#define NPOS (MAXT * BM)        // 4608 padded grouped positions

typedef unsigned long long ull;

// ---------------- device scratch (no allocations allowed) ----------------
__device__ float g_pmax_c[N_TOK];
__device__ int   g_route_c[N_TOK];
__device__ int   g_route_u[N_TOK];
__device__ int   g_dropped[N_TOK];
__device__ int   g_cnt_c[EC], g_cnt_u[EU];
__device__ int   g_cur_c[EC], g_cur_u[EU];
__device__ int   g_seg_c[EC], g_seg_u[EU];
__device__ int   g_tileE_c[MAXT], g_tileE_u[MAXT];
__device__ int   g_nt_c, g_nt_u;
__device__ int   g_idx_c[NPOS], g_idx_u[NPOS];
__device__ float g_act[(size_t)NPOS * FDIM];   // 56.6 MB intermediate activations

// ---------------- packed f32x2 helpers (FFMA2 path, sm_103a) ----------------
__device__ __forceinline__ ull ffma2(ull a, ull b, ull c) {
    ull d;
    asm("fma.rn.f32x2 %0, %1, %2, %3;" : "=l"(d) : "l"(a), "l"(b), "l"(c));
    return d;
}
__device__ __forceinline__ ull pack2_dup(float x) {
    ull d; unsigned xu = __float_as_uint(x);
    asm("mov.b64 %0, {%1, %2};" : "=l"(d) : "r"(xu), "r"(xu));
    return d;
}
__device__ __forceinline__ void unpack2(ull v, float& lo, float& hi) {
    unsigned l, h;
    asm("mov.b64 {%0, %1}, %2;" : "=r"(l), "=r"(h) : "l"(v));
    lo = __uint_as_float(l); hi = __uint_as_float(h);
}
__device__ __forceinline__ float gelu_exact(float x) {
    return 0.5f * x * (1.0f + erff(x * 0.7071067811865476f));
}

// ---------------- 0. reset counters / index arrays ----------------
__global__ void reset_kernel() {
    int i = blockIdx.x * blockDim.x + threadIdx.x;
    if (i < EC) { g_cnt_c[i] = 0; g_cur_c[i] = 0; }
    if (i < EU) { g_cnt_u[i] = 0; g_cur_u[i] = 0; }
    for (int p = i; p < NPOS; p += gridDim.x * blockDim.x) {
        g_idx_c[p] = -1;
        g_idx_u[p] = -1;
    }
}

// ---------------- 1. router: logits, softmax pmax, argmax ----------------
__global__ void router_kernel(const float* __restrict__ h,
                              const float* __restrict__ Wsc, const float* __restrict__ bsc,
                              const float* __restrict__ Wsu, const float* __restrict__ bsu) {
    int gw   = (blockIdx.x * blockDim.x + threadIdx.x) >> 5;   // one warp per token
    int lane = threadIdx.x & 31;
    if (gw >= N_TOK) return;
    const float* hr = h + (size_t)gw * HDIM;
    float a0=0,a1=0,a2=0,a3=0,u0=0,u1=0,u2=0,u3=0;
    for (int k = lane; k < HDIM; k += 32) {
        float x = hr[k];
        float4 wc = *(const float4*)(Wsc + 4 * k);   // Wsc is [H,4] row-major
        float4 wu = *(const float4*)(Wsu + 4 * k);
        a0 += x*wc.x; a1 += x*wc.y; a2 += x*wc.z; a3 += x*wc.w;
        u0 += x*wu.x; u1 += x*wu.y; u2 += x*wu.z; u3 += x*wu.w;
    }
    #pragma unroll
    for (int o = 16; o > 0; o >>= 1) {
        a0 += __shfl_down_sync(0xffffffffu, a0, o);
        a1 += __shfl_down_sync(0xffffffffu, a1, o);
        a2 += __shfl_down_sync(0xffffffffu, a2, o);
        a3 += __shfl_down_sync(0xffffffffu, a3, o);
        u0 += __shfl_down_sync(0xffffffffu, u0, o);
        u1 += __shfl_down_sync(0xffffffffu, u1, o);
        u2 += __shfl_down_sync(0xffffffffu, u2, o);
        u3 += __shfl_down_sync(0xffffffffu, u3, o);
    }
    if (lane == 0) {
        float lc[4] = {a0 + bsc[0], a1 + bsc[1], a2 + bsc[2], a3 + bsc[3]};
        float lu[4] = {u0 + bsu[0], u1 + bsu[1], u2 + bsu[2], u3 + bsu[3]};
        int rc = 0; float mc = lc[0];
        #pragma unroll
        for (int e = 1; e < EC; e++) if (lc[e] > mc) { mc = lc[e]; rc = e; }  // first-max
        float s = 0.f;
        #pragma unroll
        for (int e = 0; e < EC; e++) s += expf(lc[e] - mc);
        g_pmax_c[gw]  = 1.0f / s;          // pmax = exp(0)/sum
        g_route_c[gw] = rc;
        atomicAdd(&g_cnt_c[rc], 1);
        int ru = 0; float mu = lu[0];
        #pragma unroll
        for (int e = 1; e < EU; e++) if (lu[e] > mu) { mu = lu[e]; ru = e; }
        g_route_u[gw] = ru;
    }
}

// ---------------- 2. rank within expert group (lexsort semantics) ----------------
__global__ void drop_kernel() {
    __shared__ float sp[N_TOK];
    __shared__ unsigned char sr[N_TOK];
    int tid = threadIdx.x;
    for (int j = tid; j < N_TOK; j += blockDim.x) {
        sp[j] = g_pmax_c[j];
        sr[j] = (unsigned char)g_route_c[j];
    }
    __syncthreads();
    int i = blockIdx.x * blockDim.x + tid;   // grid covers exactly N_TOK
    float pi = sp[i];
    unsigned char re = sr[i];
    int cnt = 0;
    for (int j = 0; j < N_TOK; j++) {
        float pj = sp[j];
        bool before = (pj > pi) || (pj == pi && j < i);   // stable lexsort tie-break
        cnt += (sr[j] == re) && before;
    }
    int drp = (cnt >= CAP) ? 1 : 0;
    g_dropped[i] = drp;
    if (drp) atomicAdd(&g_cnt_u[g_route_u[i]], 1);
}

// ---------------- 3. build padded segment / tile tables ----------------
__global__ void build_tiles_kernel() {
    if (threadIdx.x == 0 && blockIdx.x == 0) {
        int base = 0, t = 0;
        for (int e = 0; e < EC; e++) {
            g_seg_c[e] = base;
            int tiles = (g_cnt_c[e] + BM - 1) / BM;
            for (int i = 0; i < tiles; i++) g_tileE_c[t++] = e;
            base += tiles * BM;
        }
        g_nt_c = t;
        base = 0; t = 0;
        for (int e = 0; e < EU; e++) {
            g_seg_u[e] = base;
            int tiles = (g_cnt_u[e] + BM - 1) / BM;
            for (int i = 0; i < tiles; i++) g_tileE_u[t++] = e;
            base += tiles * BM;
        }
        g_nt_u = t;
    }
}

// ---------------- 4. scatter tokens into grouped order ----------------
__global__ void scatter_kernel() {
    int i = blockIdx.x * blockDim.x + threadIdx.x;
    if (i >= N_TOK) return;
    int e = g_route_c[i];
    int p = g_seg_c[e] + atomicAdd(&g_cur_c[e], 1);
    g_idx_c[p] = i;
    if (g_dropped[i]) {
        int eu = g_route_u[i];
        int q = g_seg_u[eu] + atomicAdd(&g_cur_u[eu], 1);
        g_idx_u[q] = i;
    }
}

// ---------------- 5. FFN stage 1: act = gelu(gather(X) @ W1[e] + b1[e]) ----------------
__global__ __launch_bounds__(256) void ffn1_kernel(
        const float* __restrict__ X, const float* __restrict__ W1,
        const float* __restrict__ b1, int uniq) {
    const int* idx   = uniq ? g_idx_u   : g_idx_c;
    const int* tileE = uniq ? g_tileE_u : g_tileE_c;
    int nt           = uniq ? g_nt_u    : g_nt_c;
    int mt = blockIdx.y;
    if (mt >= nt) return;
    int e  = tileE[mt];
    int n0 = blockIdx.x * BN;
    const float* Wb = W1 + (size_t)e * HDIM * FDIM;   // [K=H, N=F] row-major
    const float* bb = b1 + e * FDIM;

    __shared__ float As[BK][BM];
    __shared__ float Bs[BK][BN];

    int tid  = threadIdx.x;
    int arow = tid >> 1, ak = (tid & 1) * 4;
    int tok  = idx[mt * BM + arow];
    bool aval = tok >= 0;
    const float* aptr = X + (size_t)(aval ? tok : 0) * HDIM + ak;
    int brow = tid >> 5, bn = (tid & 31) * 4;
    const float* bptr = Wb + (size_t)brow * FDIM + n0 + bn;

    int tx = tid & 15, ty = tid >> 4;
    ull acc[8][4];
    #pragma unroll
    for (int i = 0; i < 8; i++)
        #pragma unroll
        for (int j = 0; j < 4; j++) acc[i][j] = 0ull;

    const int NKT = HDIM / BK;
    float4 aF = aval ? *(const float4*)aptr : make_float4(0.f,0.f,0.f,0.f);
    float4 bF = *(const float4*)bptr;

    for (int kt = 0; kt < NKT; ++kt) {
        As[ak+0][arow] = aF.x; As[ak+1][arow] = aF.y;
        As[ak+2][arow] = aF.z; As[ak+3][arow] = aF.w;
        *(float4*)&Bs[brow][bn] = bF;
        __syncthreads();
        if (kt + 1 < NKT) {
            aF = aval ? *(const float4*)(aptr + (size_t)(kt+1)*BK) : make_float4(0.f,0.f,0.f,0.f);
            bF = *(const float4*)(bptr + (size_t)(kt+1)*BK*FDIM);
        }
        #pragma unroll
        for (int kk = 0; kk < BK; kk++) {
            float4 A0 = *(const float4*)&As[kk][ty*4];
            float4 A1 = *(const float4*)&As[kk][ty*4 + 64];
            ull B0 = *(const ull*)&Bs[kk][tx*4];
            ull B1 = *(const ull*)&Bs[kk][tx*4 + 2];
            ull B2 = *(const ull*)&Bs[kk][tx*4 + 64];
            ull B3 = *(const ull*)&Bs[kk][tx*4 + 66];
            float av[8] = {A0.x,A0.y,A0.z,A0.w,A1.x,A1.y,A1.z,A1.w};
            #pragma unroll
            for (int i = 0; i < 8; i++) {
                ull ap = pack2_dup(av[i]);
                acc[i][0] = ffma2(ap, B0, acc[i][0]);
                acc[i][1] = ffma2(ap, B1, acc[i][1]);
                acc[i][2] = ffma2(ap, B2, acc[i][2]);
                acc[i][3] = ffma2(ap, B3, acc[i][3]);
            }
        }
        __syncthreads();
    }

    int cn0 = n0 + tx * 4;
    #pragma unroll
    for (int i = 0; i < 8; i++) {
        int r = ty * 4 + (i & 3) + ((i >> 2) ? 64 : 0);
        size_t prow = (size_t)(mt * BM + r) * FDIM;
        float v0,v1,v2,v3;
        unpack2(acc[i][0], v0, v1); unpack2(acc[i][1], v2, v3);
        v0 = gelu_exact(v0 + bb[cn0+0]); v1 = gelu_exact(v1 + bb[cn0+1]);
        v2 = gelu_exact(v2 + bb[cn0+2]); v3 = gelu_exact(v3 + bb[cn0+3]);
        *(float4*)&g_act[prow + cn0] = make_float4(v0,v1,v2,v3);
        unpack2(acc[i][2], v0, v1); unpack2(acc[i][3], v2, v3);
        v0 = gelu_exact(v0 + bb[cn0+64]); v1 = gelu_exact(v1 + bb[cn0+65]);
        v2 = gelu_exact(v2 + bb[cn0+66]); v3 = gelu_exact(v3 + bb[cn0+67]);
        *(float4*)&g_act[prow + cn0 + 64] = make_float4(v0,v1,v2,v3);
    }
}

// ---------------- 6. FFN stage 2: out[tok] (=|+=) act @ W2[e] + b2[e] ----------------
__global__ __launch_bounds__(256) void ffn2_kernel(
        const float* __restrict__ W2, const float* __restrict__ b2,
        float* __restrict__ out, int uniq) {
    const int* idx   = uniq ? g_idx_u   : g_idx_c;
    const int* tileE = uniq ? g_tileE_u : g_tileE_c;
    int nt           = uniq ? g_nt_u    : g_nt_c;
    int mt = blockIdx.y;
    if (mt >= nt) return;
    int e  = tileE[mt];
    int n0 = blockIdx.x * BN;
    const float* Wb = W2 + (size_t)e * FDIM * HDIM;   // [K=F, N=H] row-major
    const float* bb = b2 + e * HDIM;

    __shared__ float As[BK][BM];
    __shared__ float Bs[BK][BN];

    int tid  = threadIdx.x;
    int arow = tid >> 1, ak = (tid & 1) * 4;
    const float* aptr = g_act + (size_t)(mt * BM + arow) * FDIM + ak;
    int brow = tid >> 5, bn = (tid & 31) * 4;
    const float* bptr = Wb + (size_t)brow * HDIM + n0 + bn;

    int tx = tid & 15, ty = tid >> 4;
    ull acc[8][4];
    #pragma unroll
    for (int i = 0; i < 8; i++)
        #pragma unroll
        for (int j = 0; j < 4; j++) acc[i][j] = 0ull;

    const int NKT = FDIM / BK;
    float4 aF = *(const float4*)aptr;
    float4 bF = *(const float4*)bptr;

    for (int kt = 0; kt < NKT; ++kt) {
        As[ak+0][arow] = aF.x; As[ak+1][arow] = aF.y;
        As[ak+2][arow] = aF.z; As[ak+3][arow] = aF.w;
        *(float4*)&Bs[brow][bn] = bF;
        __syncthreads();
        if (kt + 1 < NKT) {
            aF = *(const float4*)(aptr + (size_t)(kt+1)*BK);
            bF = *(const float4*)(bptr + (size_t)(kt+1)*BK*HDIM);
        }
        #pragma unroll
        for (int kk = 0; kk < BK; kk++) {
            float4 A0 = *(const float4*)&As[kk][ty*4];
            float4 A1 = *(const float4*)&As[kk][ty*4 + 64];
            ull B0 = *(const ull*)&Bs[kk][tx*4];
            ull B1 = *(const ull*)&Bs[kk][tx*4 + 2];
            ull B2 = *(const ull*)&Bs[kk][tx*4 + 64];
            ull B3 = *(const ull*)&Bs[kk][tx*4 + 66];
            float av[8] = {A0.x,A0.y,A0.z,A0.w,A1.x,A1.y,A1.z,A1.w};
            #pragma unroll
            for (int i = 0; i < 8; i++) {
                ull ap = pack2_dup(av[i]);
                acc[i][0] = ffma2(ap, B0, acc[i][0]);
                acc[i][1] = ffma2(ap, B1, acc[i][1]);
                acc[i][2] = ffma2(ap, B2, acc[i][2]);
                acc[i][3] = ffma2(ap, B3, acc[i][3]);
            }
        }
        __syncthreads();
    }

    int cn0 = n0 + tx * 4;
    #pragma unroll
    for (int i = 0; i < 8; i++) {
        int r   = ty * 4 + (i & 3) + ((i >> 2) ? 64 : 0);
        int tok = idx[mt * BM + r];
        if (tok < 0) continue;
        float* orow = out + (size_t)tok * HDIM;
        float v0,v1,v2,v3;
        unpack2(acc[i][0], v0, v1); unpack2(acc[i][1], v2, v3);
        v0 += bb[cn0+0]; v1 += bb[cn0+1]; v2 += bb[cn0+2]; v3 += bb[cn0+3];
        if (uniq) {
            float4 p = *(float4*)&orow[cn0];
            v0 += p.x; v1 += p.y; v2 += p.z; v3 += p.w;
        }
        *(float4*)&orow[cn0] = make_float4(v0,v1,v2,v3);
        unpack2(acc[i][2], v0, v1); unpack2(acc[i][3], v2, v3);
        v0 += bb[cn0+64]; v1 += bb[cn0+65]; v2 += bb[cn0+66]; v3 += bb[cn0+67];
        if (uniq) {
            float4 p = *(float4*)&orow[cn0 + 64];
            v0 += p.x; v1 += p.y; v2 += p.z; v3 += p.w;
        }
        *(float4*)&orow[cn0 + 64] = make_float4(v0,v1,v2,v3);
    }
}

// ---------------- launch ----------------
extern "C" void kernel_launch(void* const* d_in, const int* in_sizes, int n_in,
                              void* d_out, int out_size) {
    const float* h   = (const float*)d_in[0];
    const float* Wsc = (const float*)d_in[1];
    const float* bsc = (const float*)d_in[2];
    const float* W1c = (const float*)d_in[3];
    const float* b1c = (const float*)d_in[4];
    const float* W2c = (const float*)d_in[5];
    const float* b2c = (const float*)d_in[6];
    const float* Wsu = (const float*)d_in[7];
    const float* bsu = (const float*)d_in[8];
    const float* W1u = (const float*)d_in[9];
    const float* b1u = (const float*)d_in[10];
    const float* W2u = (const float*)d_in[11];
    const float* b2u = (const float*)d_in[12];
    float* out = (float*)d_out;

    reset_kernel<<<18, 256>>>();
    router_kernel<<<512, 256>>>(h, Wsc, bsc, Wsu, bsu);
    drop_kernel<<<16, 256>>>();
    build_tiles_kernel<<<1, 32>>>();
    scatter_kernel<<<16, 256>>>();

    // common path: every token
    ffn1_kernel<<<dim3(FDIM / BN, MAXT), 256>>>(h, W1c, b1c, 0);
    ffn2_kernel<<<dim3(HDIM / BN, MAXT), 256>>>(W2c, b2c, out, 0);
    // unique path: dropped tokens only (accumulates into out)
    ffn1_kernel<<<dim3(FDIM / BN, MAXT), 256>>>(h, W1u, b1u, 1);
    ffn2_kernel<<<dim3(HDIM / BN, MAXT), 256>>>(W2u, b2u, out, 1);
}

// round 5
// speedup vs baseline: 1.0868x; 1.0868x over previous
#include <cuda_runtime.h>
#include <math.h>
#include <stdint.h>

// ---------------- problem constants ----------------
#define N_TOK 4096
#define HDIM  768
#define FDIM  3072
#define EC    4
#define EU    4
#define CAP   1024

#define BM    128
#define BN    128
#define KC    32              // K per stage
#define ASTRIDE 36            // KC + 4 pad (stride ≡ 4 mod 32 → conflict-free frag reads)
#define MAXT  36
#define NPOS  (MAXT * BM)

// ---------------- device scratch ----------------
__device__ float g_pmax_c[N_TOK];
__device__ int   g_route_c[N_TOK];
__device__ int   g_route_u[N_TOK];
__device__ int   g_dropped[N_TOK];
__device__ int   g_cnt_c[EC], g_cnt_u[EU];
__device__ int   g_cur_c[EC], g_cur_u[EU];
__device__ int   g_seg_c[EC], g_seg_u[EU];
__device__ int   g_tileE_c[MAXT], g_tileE_u[MAXT];
__device__ int   g_nt_c, g_nt_u;
__device__ int   g_idx_c[NPOS], g_idx_u[NPOS];
__device__ float g_hr[(size_t)N_TOK * HDIM];                 // rna-rounded hidden states
__device__ float g_act[(size_t)NPOS * FDIM];                 // FFN1 out (rna-rounded)
__device__ float g_w1t[2][(size_t)EC * FDIM * HDIM];         // W1 permuted frag order
__device__ float g_w2t[2][(size_t)EC * FDIM * HDIM];         // W2 permuted frag order

// ---------------- helpers ----------------
__device__ __forceinline__ uint32_t smem_u32(const void* p) {
    uint32_t a;
    asm("{ .reg .u64 t; cvta.to.shared.u64 t, %1; cvt.u32.u64 %0, t; }" : "=r"(a) : "l"(p));
    return a;
}
__device__ __forceinline__ float rna_tf32(float v) {
    uint32_t u;
    asm("cvt.rna.tf32.f32 %0, %1;" : "=r"(u) : "f"(v));
    return __uint_as_float(u);
}
__device__ __forceinline__ float gelu_exact(float x) {
    return 0.5f * x * (1.0f + erff(x * 0.7071067811865476f));
}
#define CPA16(dst, src)  asm volatile("cp.async.cg.shared.global [%0], [%1], 16;" :: "r"(dst), "l"(src))
#define CPCOMMIT()       asm volatile("cp.async.commit_group;" ::: "memory")
#define CPWAIT1()        asm volatile("cp.async.wait_group 1;" ::: "memory")

__device__ __forceinline__ void mma_tf32_16x8x8(float* c, const float* a, float2 b) {
    asm volatile(
        "mma.sync.aligned.m16n8k8.row.col.f32.tf32.tf32.f32 "
        "{%0,%1,%2,%3}, {%4,%5,%6,%7}, {%8,%9}, {%0,%1,%2,%3};"
        : "+f"(c[0]), "+f"(c[1]), "+f"(c[2]), "+f"(c[3])
        : "r"(__float_as_uint(a[0])), "r"(__float_as_uint(a[1])),
          "r"(__float_as_uint(a[2])), "r"(__float_as_uint(a[3])),
          "r"(__float_as_uint(b.x)),  "r"(__float_as_uint(b.y)));
}

// ---------------- 0. reset ----------------
__global__ void reset_kernel() {
    int i = blockIdx.x * blockDim.x + threadIdx.x;
    if (i < EC) { g_cnt_c[i] = 0; g_cur_c[i] = 0; }
    if (i < EU) { g_cnt_u[i] = 0; g_cur_u[i] = 0; }
    for (int p = i; p < NPOS; p += gridDim.x * blockDim.x) {
        g_idx_c[p] = -1;
        g_idx_u[p] = -1;
    }
}

// ---------------- 1. router ----------------
__global__ void router_kernel(const float* __restrict__ h,
                              const float* __restrict__ Wsc, const float* __restrict__ bsc,
                              const float* __restrict__ Wsu, const float* __restrict__ bsu) {
    int gw   = (blockIdx.x * blockDim.x + threadIdx.x) >> 5;
    int lane = threadIdx.x & 31;
    if (gw >= N_TOK) return;
    const float* hr = h + (size_t)gw * HDIM;
    float a0=0,a1=0,a2=0,a3=0,u0=0,u1=0,u2=0,u3=0;
    for (int k = lane; k < HDIM; k += 32) {
        float x = hr[k];
        float4 wc = *(const float4*)(Wsc + 4 * k);
        float4 wu = *(const float4*)(Wsu + 4 * k);
        a0 += x*wc.x; a1 += x*wc.y; a2 += x*wc.z; a3 += x*wc.w;
        u0 += x*wu.x; u1 += x*wu.y; u2 += x*wu.z; u3 += x*wu.w;
    }
    #pragma unroll
    for (int o = 16; o > 0; o >>= 1) {
        a0 += __shfl_down_sync(0xffffffffu, a0, o);
        a1 += __shfl_down_sync(0xffffffffu, a1, o);
        a2 += __shfl_down_sync(0xffffffffu, a2, o);
        a3 += __shfl_down_sync(0xffffffffu, a3, o);
        u0 += __shfl_down_sync(0xffffffffu, u0, o);
        u1 += __shfl_down_sync(0xffffffffu, u1, o);
        u2 += __shfl_down_sync(0xffffffffu, u2, o);
        u3 += __shfl_down_sync(0xffffffffu, u3, o);
    }
    if (lane == 0) {
        float lc[4] = {a0 + bsc[0], a1 + bsc[1], a2 + bsc[2], a3 + bsc[3]};
        float lu[4] = {u0 + bsu[0], u1 + bsu[1], u2 + bsu[2], u3 + bsu[3]};
        int rc = 0; float mc = lc[0];
        #pragma unroll
        for (int e = 1; e < EC; e++) if (lc[e] > mc) { mc = lc[e]; rc = e; }
        float s = 0.f;
        #pragma unroll
        for (int e = 0; e < EC; e++) s += expf(lc[e] - mc);
        g_pmax_c[gw]  = 1.0f / s;
        g_route_c[gw] = rc;
        atomicAdd(&g_cnt_c[rc], 1);
        int ru = 0; float mu = lu[0];
        #pragma unroll
        for (int e = 1; e < EU; e++) if (lu[e] > mu) { mu = lu[e]; ru = e; }
        g_route_u[gw] = ru;
    }
}

// ---------------- 2. capacity drop (lexsort rank) ----------------
__global__ void drop_kernel() {
    __shared__ float sp[N_TOK];
    __shared__ unsigned char sr[N_TOK];
    int tid = threadIdx.x;
    for (int j = tid; j < N_TOK; j += blockDim.x) {
        sp[j] = g_pmax_c[j];
        sr[j] = (unsigned char)g_route_c[j];
    }
    __syncthreads();
    int i = blockIdx.x * blockDim.x + tid;
    float pi = sp[i];
    unsigned char re = sr[i];
    int cnt = 0;
    for (int j = 0; j < N_TOK; j++) {
        float pj = sp[j];
        bool before = (pj > pi) || (pj == pi && j < i);
        cnt += (sr[j] == re) && before;
    }
    int drp = (cnt >= CAP) ? 1 : 0;
    g_dropped[i] = drp;
    if (drp) atomicAdd(&g_cnt_u[g_route_u[i]], 1);
}

// ---------------- 3. tile tables ----------------
__global__ void build_tiles_kernel() {
    if (threadIdx.x == 0 && blockIdx.x == 0) {
        int base = 0, t = 0;
        for (int e = 0; e < EC; e++) {
            g_seg_c[e] = base;
            int tiles = (g_cnt_c[e] + BM - 1) / BM;
            for (int i = 0; i < tiles; i++) g_tileE_c[t++] = e;
            base += tiles * BM;
        }
        g_nt_c = t;
        base = 0; t = 0;
        for (int e = 0; e < EU; e++) {
            g_seg_u[e] = base;
            int tiles = (g_cnt_u[e] + BM - 1) / BM;
            for (int i = 0; i < tiles; i++) g_tileE_u[t++] = e;
            base += tiles * BM;
        }
        g_nt_u = t;
    }
}

// ---------------- 4. scatter ----------------
__global__ void scatter_kernel() {
    int i = blockIdx.x * blockDim.x + threadIdx.x;
    if (i >= N_TOK) return;
    int e = g_route_c[i];
    int p = g_seg_c[e] + atomicAdd(&g_cur_c[e], 1);
    g_idx_c[p] = i;
    if (g_dropped[i]) {
        int eu = g_route_u[i];
        int q = g_seg_u[eu] + atomicAdd(&g_cur_u[eu], 1);
        g_idx_u[q] = i;
    }
}

// ---------------- 5a. round hidden states to tf32 (rna) ----------------
__global__ void round_h_kernel(const float* __restrict__ h) {
    int i = blockIdx.x * blockDim.x + threadIdx.x;
    if (i < N_TOK * HDIM) g_hr[i] = rna_tf32(h[i]);
}

// ---------------- 5b. permute weights into mma B-fragment order ----------------
// src [E][Kd][Nd] row-major -> dst [E][Nd/8][Kd/8][lane32][2] with rna tf32 rounding.
// dst pair for (nb, kb, lane) = { src[kb*8 + lane%4][nb*8 + lane/4],
//                                 src[kb*8 + lane%4 + 4][nb*8 + lane/4] }
__global__ void permute_kernel(const float* __restrict__ src, int which, int Kd, int Nd) {
    __shared__ float t[32][33];
    float* dst = (which < 2) ? g_w1t[which] : g_w2t[which - 2];
    int e = blockIdx.z;
    const float* s = src + (size_t)e * Kd * Nd;
    float* d = dst + (size_t)e * Kd * Nd;
    int k0 = blockIdx.y * 32, n0 = blockIdx.x * 32;
    int tx = threadIdx.x, ty = threadIdx.y;      // 32 x 8
    for (int i = ty; i < 32; i += 8)
        t[i][tx] = s[(size_t)(k0 + i) * Nd + n0 + tx];
    __syncthreads();
    int tt = ty * 32 + tx;                       // 0..255 -> one float4 each
    int fr = tt >> 4, mm = tt & 15;              // frag 0..15, lane-pair 0..15
    int nb = fr >> 2, kb = fr & 3;
    int l0 = mm * 2, l1 = l0 + 1;
    int na = nb * 8 + (l0 >> 2), ka = kb * 8 + (l0 & 3);
    int nbq = nb * 8 + (l1 >> 2), kbq = kb * 8 + (l1 & 3);
    float4 v;
    v.x = rna_tf32(t[ka][na]);      v.y = rna_tf32(t[ka + 4][na]);
    v.z = rna_tf32(t[kbq][nbq]);    v.w = rna_tf32(t[kbq + 4][nbq]);
    size_t base = ((size_t)(n0 / 8 + nb) * (Kd / 8) + (k0 / 8 + kb)) * 64 + l0 * 2;
    *(float4*)(d + base) = v;
}

// ---------------- 6. FFN1: g_act = rna(gelu(gather(g_hr) @ W1 + b1)) ----------------
__global__ void __launch_bounds__(256, 2) ffn1_mma(const float* __restrict__ b1, int uniq) {
    extern __shared__ float sm[];
    int nt = uniq ? g_nt_u : g_nt_c;
    int mt = blockIdx.y;
    if (mt >= nt) return;
    const int* idx = uniq ? g_idx_u : g_idx_c;
    int e  = (uniq ? g_tileE_u : g_tileE_c)[mt];
    int n0 = blockIdx.x * BN;
    const float* Bw = g_w1t[uniq] + (size_t)e * FDIM * HDIM;
    const float* bb = b1 + e * FDIM;

    float* A0s = sm;
    float* A1s = sm + BM * ASTRIDE;
    float* B0s = sm + 2 * BM * ASTRIDE;
    float* B1s = B0s + KC * BN;
    uint32_t A0a = smem_u32(A0s), A1a = smem_u32(A1s);
    uint32_t B0a = smem_u32(B0s), B1a = smem_u32(B1s);

    int tid = threadIdx.x;
    int arow = tid >> 1, ah = (tid & 1) * 16;
    int tokr = idx[mt * BM + arow];
    const float* aptr = g_hr + (size_t)(tokr < 0 ? 0 : tokr) * HDIM + ah;
    uint32_t adst = (uint32_t)(arow * ASTRIDE + ah) * 4u;

    const int NST = HDIM / KC;   // 24
    #define FFN1_ISSUE(s) do {                                                    \
        uint32_t Aa = ((s) & 1) ? A1a : A0a;                                      \
        uint32_t Ba = ((s) & 1) ? B1a : B0a;                                      \
        const float* ap = aptr + (s) * KC;                                        \
        _Pragma("unroll")                                                         \
        for (int i = 0; i < 4; i++) CPA16(Aa + adst + i * 16u, ap + i * 4);       \
        _Pragma("unroll")                                                         \
        for (int i = 0; i < 4; i++) {                                             \
            int ft = i * 256 + tid;                                               \
            int chunk = ft >> 4, slot = ft & 15;                                  \
            int nb = chunk >> 2, kb = chunk & 3;                                  \
            const float* bp = Bw + ((size_t)(n0 / 8 + nb) * (HDIM / 8)            \
                                    + (s) * 4 + kb) * 64 + slot * 4;              \
            CPA16(Ba + (uint32_t)(chunk * 64 + slot * 4) * 4u, bp);               \
        }                                                                         \
    } while (0)

    FFN1_ISSUE(0); CPCOMMIT();
    FFN1_ISSUE(1); CPCOMMIT();

    int wid = tid >> 5, lane = tid & 31;
    int wm = wid & 3, wn = wid >> 2;
    int r4 = lane >> 2, kl = lane & 3;

    float acc[2][8][4];
    #pragma unroll
    for (int m = 0; m < 2; m++)
        #pragma unroll
        for (int j = 0; j < 8; j++)
            #pragma unroll
            for (int q = 0; q < 4; q++) acc[m][j][q] = 0.f;

    for (int s = 0; s < NST; s++) {
        CPWAIT1();
        __syncthreads();
        const float* As = (s & 1) ? A1s : A0s;
        const float* Bs = (s & 1) ? B1s : B0s;
        #pragma unroll
        for (int kb = 0; kb < 4; kb++) {
            const float* Ab = As + (wm * 32 + r4) * ASTRIDE + kb * 8;
            float a[2][4];
            #pragma unroll
            for (int m = 0; m < 2; m++) {
                const float* Am = Ab + m * 16 * ASTRIDE;
                a[m][0] = Am[kl];
                a[m][1] = Am[8 * ASTRIDE + kl];
                a[m][2] = Am[kl + 4];
                a[m][3] = Am[8 * ASTRIDE + kl + 4];
            }
            #pragma unroll
            for (int j = 0; j < 8; j++) {
                // smem B chunk layout is nb*4 + kb (nb = wn*8 + j)
                float2 b = ((const float2*)Bs)[((wn * 8 + j) * 4 + kb) * 32 + lane];
                mma_tf32_16x8x8(acc[0][j], a[0], b);
                mma_tf32_16x8x8(acc[1][j], a[1], b);
            }
        }
        __syncthreads();
        if (s + 2 < NST) FFN1_ISSUE(s + 2);
        CPCOMMIT();
    }
    #undef FFN1_ISSUE

    // epilogue: bias + gelu + rna -> g_act
    #pragma unroll
    for (int m = 0; m < 2; m++) {
        int r0 = mt * BM + wm * 32 + m * 16 + r4;
        #pragma unroll
        for (int j = 0; j < 8; j++) {
            int col = n0 + wn * 64 + j * 8 + 2 * kl;
            float bq0 = bb[col], bq1 = bb[col + 1];
            float2 v;
            v.x = rna_tf32(gelu_exact(acc[m][j][0] + bq0));
            v.y = rna_tf32(gelu_exact(acc[m][j][1] + bq1));
            *(float2*)(g_act + (size_t)r0 * FDIM + col) = v;
            v.x = rna_tf32(gelu_exact(acc[m][j][2] + bq0));
            v.y = rna_tf32(gelu_exact(acc[m][j][3] + bq1));
            *(float2*)(g_act + (size_t)(r0 + 8) * FDIM + col) = v;
        }
    }
}

// ---------------- 7. FFN2: out[tok] (=|+=) g_act @ W2 + b2 ----------------
__global__ void __launch_bounds__(256, 2) ffn2_mma(const float* __restrict__ b2,
                                                   float* __restrict__ out, int uniq) {
    extern __shared__ float sm[];
    int nt = uniq ? g_nt_u : g_nt_c;
    int mt = blockIdx.y;
    if (mt >= nt) return;
    const int* idx = uniq ? g_idx_u : g_idx_c;
    int e  = (uniq ? g_tileE_u : g_tileE_c)[mt];
    int n0 = blockIdx.x * BN;
    const float* Bw = g_w2t[uniq] + (size_t)e * FDIM * HDIM;
    const float* bb = b2 + e * HDIM;

    float* A0s = sm;
    float* A1s = sm + BM * ASTRIDE;
    float* B0s = sm + 2 * BM * ASTRIDE;
    float* B1s = B0s + KC * BN;
    uint32_t A0a = smem_u32(A0s), A1a = smem_u32(A1s);
    uint32_t B0a = smem_u32(B0s), B1a = smem_u32(B1s);

    int tid = threadIdx.x;
    int arow = tid >> 1, ah = (tid & 1) * 16;
    const float* aptr = g_act + (size_t)(mt * BM + arow) * FDIM + ah;
    uint32_t adst = (uint32_t)(arow * ASTRIDE + ah) * 4u;

    const int NST = FDIM / KC;   // 96
    #define FFN2_ISSUE(s) do {                                                    \
        uint32_t Aa = ((s) & 1) ? A1a : A0a;                                      \
        uint32_t Ba = ((s) & 1) ? B1a : B0a;                                      \
        const float* ap = aptr + (s) * KC;                                        \
        _Pragma("unroll")                                                         \
        for (int i = 0; i < 4; i++) CPA16(Aa + adst + i * 16u, ap + i * 4);       \
        _Pragma("unroll")                                                         \
        for (int i = 0; i < 4; i++) {                                             \
            int ft = i * 256 + tid;                                               \
            int chunk = ft >> 4, slot = ft & 15;                                  \
            int nb = chunk >> 2, kb = chunk & 3;                                  \
            const float* bp = Bw + ((size_t)(n0 / 8 + nb) * (FDIM / 8)            \
                                    + (s) * 4 + kb) * 64 + slot * 4;              \
            CPA16(Ba + (uint32_t)(chunk * 64 + slot * 4) * 4u, bp);               \
        }                                                                         \
    } while (0)

    FFN2_ISSUE(0); CPCOMMIT();
    FFN2_ISSUE(1); CPCOMMIT();

    int wid = tid >> 5, lane = tid & 31;
    int wm = wid & 3, wn = wid >> 2;
    int r4 = lane >> 2, kl = lane & 3;

    float acc[2][8][4];
    #pragma unroll
    for (int m = 0; m < 2; m++)
        #pragma unroll
        for (int j = 0; j < 8; j++)
            #pragma unroll
            for (int q = 0; q < 4; q++) acc[m][j][q] = 0.f;

    for (int s = 0; s < NST; s++) {
        CPWAIT1();
        __syncthreads();
        const float* As = (s & 1) ? A1s : A0s;
        const float* Bs = (s & 1) ? B1s : B0s;
        #pragma unroll
        for (int kb = 0; kb < 4; kb++) {
            const float* Ab = As + (wm * 32 + r4) * ASTRIDE + kb * 8;
            float a[2][4];
            #pragma unroll
            for (int m = 0; m < 2; m++) {
                const float* Am = Ab + m * 16 * ASTRIDE;
                a[m][0] = Am[kl];
                a[m][1] = Am[8 * ASTRIDE + kl];
                a[m][2] = Am[kl + 4];
                a[m][3] = Am[8 * ASTRIDE + kl + 4];
            }
            #pragma unroll
            for (int j = 0; j < 8; j++) {
                // smem B chunk layout is nb*4 + kb (nb = wn*8 + j)
                float2 b = ((const float2*)Bs)[((wn * 8 + j) * 4 + kb) * 32 + lane];
                mma_tf32_16x8x8(acc[0][j], a[0], b);
                mma_tf32_16x8x8(acc[1][j], a[1], b);
            }
        }
        __syncthreads();
        if (s + 2 < NST) FFN2_ISSUE(s + 2);
        CPCOMMIT();
    }
    #undef FFN2_ISSUE

    // epilogue: bias (+ accumulate for unique) -> out rows via idx
    #pragma unroll
    for (int m = 0; m < 2; m++) {
        int rbase = mt * BM + wm * 32 + m * 16 + r4;
        #pragma unroll
        for (int rr = 0; rr < 2; rr++) {
            int tok = idx[rbase + rr * 8];
            if (tok < 0) continue;
            float* orow = out + (size_t)tok * HDIM;
            #pragma unroll
            for (int j = 0; j < 8; j++) {
                int col = n0 + wn * 64 + j * 8 + 2 * kl;
                float2 v;
                v.x = acc[m][j][rr * 2 + 0] + bb[col];
                v.y = acc[m][j][rr * 2 + 1] + bb[col + 1];
                if (uniq) {
                    float2 p = *(float2*)(orow + col);
                    v.x += p.x; v.y += p.y;
                }
                *(float2*)(orow + col) = v;
            }
        }
    }
}

// ---------------- launch ----------------
extern "C" void kernel_launch(void* const* d_in, const int* in_sizes, int n_in,
                              void* d_out, int out_size) {
    const float* h   = (const float*)d_in[0];
    const float* Wsc = (const float*)d_in[1];
    const float* bsc = (const float*)d_in[2];
    const float* W1c = (const float*)d_in[3];
    const float* b1c = (const float*)d_in[4];
    const float* W2c = (const float*)d_in[5];
    const float* b2c = (const float*)d_in[6];
    const float* Wsu = (const float*)d_in[7];
    const float* bsu = (const float*)d_in[8];
    const float* W1u = (const float*)d_in[9];
    const float* b1u = (const float*)d_in[10];
    const float* W2u = (const float*)d_in[11];
    const float* b2u = (const float*)d_in[12];
    float* out = (float*)d_out;

    const int SMEM = (2 * BM * ASTRIDE + 2 * KC * BN) * 4;   // 69632 B
    cudaFuncSetAttribute(ffn1_mma, cudaFuncAttributeMaxDynamicSharedMemorySize, SMEM);
    cudaFuncSetAttribute(ffn2_mma, cudaFuncAttributeMaxDynamicSharedMemorySize, SMEM);

    // weight permutes (+ tf32 rna rounding)
    dim3 pb(32, 8);
    permute_kernel<<<dim3(FDIM / 32, HDIM / 32, EC), pb>>>(W1c, 0, HDIM, FDIM);
    permute_kernel<<<dim3(FDIM / 32, HDIM / 32, EU), pb>>>(W1u, 1, HDIM, FDIM);
    permute_kernel<<<dim3(HDIM / 32, FDIM / 32, EC), pb>>>(W2c, 2, FDIM, HDIM);
    permute_kernel<<<dim3(HDIM / 32, FDIM / 32, EU), pb>>>(W2u, 3, FDIM, HDIM);
    round_h_kernel<<<(N_TOK * HDIM + 255) / 256, 256>>>(h);

    // routing
    reset_kernel<<<18, 256>>>();
    router_kernel<<<512, 256>>>(h, Wsc, bsc, Wsu, bsu);
    drop_kernel<<<16, 256>>>();
    build_tiles_kernel<<<1, 32>>>();
    scatter_kernel<<<16, 256>>>();

    // common path
    ffn1_mma<<<dim3(FDIM / BN, MAXT), 256, SMEM>>>(b1c, 0);
    ffn2_mma<<<dim3(HDIM / BN, MAXT), 256, SMEM>>>(b2c, out, 0);
    // unique path (accumulates)
    ffn1_mma<<<dim3(FDIM / BN, MAXT), 256, SMEM>>>(b1u, 1);
    ffn2_mma<<<dim3(HDIM / BN, MAXT), 256, SMEM>>>(b2u, out, 1);
}